// round 10
// baseline (speedup 1.0000x reference)
#include <cuda_runtime.h>
#include <math.h>

#define Bz 16
#define Cc 64
#define Hh 128
#define Ww 128
#define HWp (Hh*Ww)
#define EPSV 2.220446049250313e-16f
#define NBAND 16
#define RCG 4            // router channel groups
#define RCH 16

// ---- device scratch ----
__device__ float g_part[Bz * NBAND * RCG * 8];
__device__ int   g_sel[Bz * 2];
__device__ float g_w1[Bz];

typedef unsigned long long u64;

__device__ __forceinline__ u64 pk(float lo, float hi) {
    u64 r; asm("mov.b64 %0, {%1,%2};" : "=l"(r) : "f"(lo), "f"(hi)); return r;
}
__device__ __forceinline__ void upk(u64 v, float& lo, float& hi) {
    asm("mov.b64 {%0,%1}, %2;" : "=f"(lo), "=f"(hi) : "l"(v));
}
__device__ __forceinline__ void fma2(u64& d, u64 a, u64 b) {
    asm("fma.rn.f32x2 %0, %1, %2, %0;" : "+l"(d) : "l"(a), "l"(b));
}

// ============================================================
// Router (R5 version, measured 83.6us): conv7x7 partial over 16 channels
// + logit partials. grid (Bz, NBAND, RCG), block 256. 8-row bands,
// double-buffered channel tiles.
// ============================================================
#define RT_ROWS 14
#define RT_COLS 136
#define RT_ELEM (RT_ROWS * RT_COLS)   // 1904

__global__ __launch_bounds__(256) void router_kernel(
    const float* __restrict__ x,   // [B,C,H,W]
    const float* __restrict__ rw,  // [1,C,7,7]
    const float* __restrict__ rb,  // [1]
    const float* __restrict__ wg)  // [HW, E]
{
    __shared__ float sW[RCH * 49];
    __shared__ __align__(16) float sT[2][RT_ELEM];
    __shared__ float sPart[8][8];

    int b    = blockIdx.x;
    int band = blockIdx.y;
    int cg   = blockIdx.z;
    int h0   = band * 8;
    int t    = threadIdx.x;
    int row  = t >> 5;      // 0..7
    int wq   = t & 31;
    int ws   = wq * 4;

    for (int i = t; i < RCH * 49; i += 256)
        sW[i] = rw[cg * RCH * 49 + i];

    const float* xb = x + ((long long)b * Cc + cg * RCH) * HWp;

    float pf[8];
    #pragma unroll
    for (int k = 0; k < 8; ++k) {
        int idx = t + k * 256;
        float v = 0.f;
        if (idx < RT_ELEM) {
            int rr  = idx / RT_COLS;
            int col = idx - rr * RT_COLS;
            int gh = h0 - 3 + rr;
            int gw = col - 3;
            if (col < 134 && gh >= 0 && gh < Hh && gw >= 0 && gw < Ww)
                v = xb[gh * Ww + gw];
        }
        pf[k] = v;
    }

    u64 acc01 = pk(0.f, 0.f);
    u64 acc23 = pk(0.f, 0.f);

    for (int c = 0; c < RCH; ++c) {
        int buf = c & 1;
        #pragma unroll
        for (int k = 0; k < 8; ++k) {
            int idx = t + k * 256;
            if (idx < RT_ELEM) sT[buf][idx] = pf[k];
        }
        __syncthreads();
        if (c + 1 < RCH) {
            const float* xc = xb + (long long)(c + 1) * HWp;
            #pragma unroll
            for (int k = 0; k < 8; ++k) {
                int idx = t + k * 256;
                float v = 0.f;
                if (idx < RT_ELEM) {
                    int rr  = idx / RT_COLS;
                    int col = idx - rr * RT_COLS;
                    int gh = h0 - 3 + rr;
                    int gw = col - 3;
                    if (col < 134 && gh >= 0 && gh < Hh && gw >= 0 && gw < Ww)
                        v = xc[gh * Ww + gw];
                }
                pf[k] = v;
            }
        }
        const float* tb = sT[buf];
        const float* wc = sW + c * 49;
        #pragma unroll
        for (int dh = 0; dh < 7; ++dh) {
            u64 w7[7];
            #pragma unroll
            for (int dw = 0; dw < 7; ++dw) {
                float w = wc[dh * 7 + dw];
                w7[dw] = pk(w, w);
            }
            const float* rp = tb + (row + dh) * RT_COLS + ws;
            float4 v0 = *reinterpret_cast<const float4*>(rp);
            float4 v1 = *reinterpret_cast<const float4*>(rp + 4);
            float2 v2 = *reinterpret_cast<const float2*>(rp + 8);
            float tt[10];
            tt[0]=v0.x; tt[1]=v0.y; tt[2]=v0.z; tt[3]=v0.w;
            tt[4]=v1.x; tt[5]=v1.y; tt[6]=v1.z; tt[7]=v1.w;
            tt[8]=v2.x; tt[9]=v2.y;
            u64 p[9];
            #pragma unroll
            for (int j = 0; j < 9; ++j) p[j] = pk(tt[j], tt[j+1]);
            #pragma unroll
            for (int dw = 0; dw < 7; ++dw) {
                fma2(acc01, p[dw],     w7[dw]);
                fma2(acc23, p[dw + 2], w7[dw]);
            }
        }
    }

    float rbv = (cg == 0) ? rb[0] : 0.f;
    float rv[4];
    upk(acc01, rv[0], rv[1]);
    upk(acc23, rv[2], rv[3]);
    #pragma unroll
    for (int px = 0; px < 4; ++px) rv[px] += rbv;

    float lacc[8];
    #pragma unroll
    for (int e = 0; e < 8; ++e) lacc[e] = 0.f;
    int h = h0 + row;
    #pragma unroll
    for (int px = 0; px < 4; ++px) {
        int p = h * Ww + ws + px;
        const float4* wp = reinterpret_cast<const float4*>(wg + (long long)p * 8);
        float4 a  = wp[0];
        float4 bb = wp[1];
        float r = rv[px];
        lacc[0] += r * a.x;  lacc[1] += r * a.y;  lacc[2] += r * a.z;  lacc[3] += r * a.w;
        lacc[4] += r * bb.x; lacc[5] += r * bb.y; lacc[6] += r * bb.z; lacc[7] += r * bb.w;
    }

    int lane = t & 31, warp = t >> 5;
    #pragma unroll
    for (int e = 0; e < 8; ++e) {
        float v = lacc[e];
        #pragma unroll
        for (int off = 16; off; off >>= 1) v += __shfl_down_sync(0xffffffffu, v, off);
        if (lane == 0) sPart[warp][e] = v;
    }
    __syncthreads();
    if (t < 8) {
        float s = 0.f;
        #pragma unroll
        for (int w2 = 0; w2 < 8; ++w2) s += sPart[w2][t];
        g_part[(((b * NBAND) + band) * RCG + cg) * 8 + t] = s;
    }
}

// ============================================================
// Gating: logits -> top-2 -> gates, deterministic loss.
// ============================================================
__global__ void gate_kernel(float* __restrict__ out, long long loss_idx)
{
    __shared__ float sg0[Bz], sg1[Bz];
    __shared__ int   si0[Bz], si1[Bz];
    int t = threadIdx.x;

    if (t < Bz) {
        float l[8];
        #pragma unroll
        for (int e = 0; e < 8; ++e) {
            float s = 0.f;
            for (int k = 0; k < NBAND * RCG; ++k)
                s += g_part[(t * NBAND * RCG + k) * 8 + e];
            l[e] = s;
        }
        int i0 = 0; float m0 = l[0];
        #pragma unroll
        for (int e = 1; e < 8; ++e) if (l[e] > m0) { m0 = l[e]; i0 = e; }
        int i1 = (i0 == 0) ? 1 : 0; float m1 = l[i1];
        #pragma unroll
        for (int e = 0; e < 8; ++e)
            if (e != i0 && l[e] > m1) { m1 = l[e]; i1 = e; }
        float ex = expf(m1 - m0);
        float g0 = 1.f / (1.f + ex);
        float g1 = ex / (1.f + ex);
        g_sel[t * 2]     = i0;
        g_sel[t * 2 + 1] = i1;
        g_w1[t] = (g1 > 0.f) ? 1.f : 0.f;
        si0[t] = i0; si1[t] = i1; sg0[t] = g0; sg1[t] = g1;
    }
    __syncthreads();
    if (t == 0) {
        float imp[8]; float ldc[8];
        #pragma unroll
        for (int e = 0; e < 8; ++e) { imp[e] = 0.f; ldc[e] = 0.f; }
        for (int bb = 0; bb < Bz; ++bb) {
            imp[si0[bb]] += sg0[bb];
            imp[si1[bb]] += sg1[bb];
            ldc[si0[bb]] += 1.f;
            if (sg1[bb] > 0.f) ldc[si1[bb]] += 1.f;
        }
        float mi = 0.f, ml = 0.f;
        for (int e = 0; e < 8; ++e) { mi += imp[e]; ml += ldc[e]; }
        mi *= 0.125f; ml *= 0.125f;
        float vi = 0.f, vl = 0.f;
        for (int e = 0; e < 8; ++e) {
            float d  = imp[e] - mi; vi += d * d;
            float dl = ldc[e] - ml; vl += dl * dl;
        }
        vi *= (1.f / 7.f); vl *= (1.f / 7.f);
        float loss = (vi / (mi * mi + 1e-10f) + vl / (ml * ml + 1e-10f)) * 0.01f;
        out[loss_idx] = loss;
    }
}

// ============================================================
// Main fused kernel v5: one warp-task per warp (no serial channel loop).
// Block = 4 ch x 2 rows x 128 px; 8 warps, warp = (ch 0..3, row 0..1),
// lane = px-quad. 4 blocks/SM (launch_bounds 256,4) => 32 warps/SM.
// ============================================================
#define MC4 4                     // channels per block
#define MROW 8                    // tile rows (2 + 6 halo)
#define MCOL 136                  // 134 used
#define MTILE (MC4 * MROW * MCOL) // 4352 words

__global__ __launch_bounds__(256, 4) void main_kernel(
    const float* __restrict__ x,    // [B,C,H,W]
    const float* __restrict__ ew,   // [E,C,1,7,7]
    const float* __restrict__ eb,   // [E,C]
    const float* __restrict__ sw,   // [C,1,7,7]
    const float* __restrict__ sb,   // [C]
    float* __restrict__ out)        // [B,HW,C]
{
    __shared__ __align__(16) float  sIn[MTILE];            // 17408 B
    __shared__ __align__(8)  float2 sWd[3 * MC4 * 49];     // 4704 B
    __shared__ __align__(16) float  sOut[MC4 * 2 * 128];   // 4096 B [cl][row][px]

    int hb = blockIdx.x;          // h-strip (2 rows)
    int cg = blockIdx.y;          // channel group (4 ch)
    int b  = blockIdx.z;
    int h0 = hb * 2;
    int t  = threadIdx.x;
    int w  = t >> 5;              // warp 0..7
    int qx = t & 31;              // px-quad
    int cl = w >> 1;              // local channel 0..3
    int r  = w & 1;               // output row 0..1

    int e0  = g_sel[b * 2];
    int e1i = g_sel[b * 2 + 1];
    float w1 = g_w1[b];

    const float* xb = x + ((long long)b * Cc + cg * MC4) * HWp;

    // ---- load tile: 4 ch x 8 rows x 134 cols ----
    for (int idx = t; idx < MTILE; idx += 256) {
        int c   = idx / (MROW * MCOL);
        int rem = idx - c * (MROW * MCOL);
        int rr  = rem / MCOL;
        int col = rem - rr * MCOL;
        int gh = h0 - 3 + rr;
        int gw = col - 3;
        float v = 0.f;
        if (gh >= 0 && gh < Hh && gw >= 0 && gw < Ww)
            v = xb[c * HWp + gh * Ww + gw];
        sIn[idx] = v;
    }
    // ---- duplicated weights [f][cl][49] as float2 ----
    for (int idx = t; idx < 3 * MC4 * 49; idx += 256) {
        int f   = idx / (MC4 * 49);
        int rem = idx - f * (MC4 * 49);
        int c2  = rem / 49;
        int k   = rem - c2 * 49;
        int gc  = cg * MC4 + c2;
        float wv = (f == 0) ? sw[gc * 49 + k]
                 : (f == 1) ? ew[e0  * (Cc * 49) + gc * 49 + k]
                            : ew[e1i * (Cc * 49) + gc * 49 + k];
        sWd[idx] = make_float2(wv, wv);
    }
    __syncthreads();

    // ---- compute: one (channel, row) per warp ----
    const float* inc = sIn + cl * (MROW * MCOL) + qx * 4;
    const u64* wB = reinterpret_cast<const u64*>(sWd) + cl * 49;

    u64 acc[3][2];
    u64 z = pk(0.f, 0.f);
    #pragma unroll
    for (int f = 0; f < 3; ++f) { acc[f][0] = z; acc[f][1] = z; }

    #pragma unroll
    for (int dh = 0; dh < 7; ++dh) {
        const float* rp = inc + (r + dh) * MCOL;
        float4 v0 = *reinterpret_cast<const float4*>(rp);
        float4 v1 = *reinterpret_cast<const float4*>(rp + 4);
        float2 v2 = *reinterpret_cast<const float2*>(rp + 8);
        float tt[10];
        tt[0]=v0.x; tt[1]=v0.y; tt[2]=v0.z; tt[3]=v0.w;
        tt[4]=v1.x; tt[5]=v1.y; tt[6]=v1.z; tt[7]=v1.w;
        tt[8]=v2.x; tt[9]=v2.y;
        u64 p[9];
        #pragma unroll
        for (int j = 0; j < 9; ++j) p[j] = pk(tt[j], tt[j+1]);
        #pragma unroll
        for (int f = 0; f < 3; ++f) {
            const u64* wf = wB + f * (MC4 * 49) + dh * 7;
            #pragma unroll
            for (int dw = 0; dw < 7; ++dw) {
                u64 wv = wf[dw];                 // LDS.64 broadcast
                fma2(acc[f][0], p[dw],     wv);
                fma2(acc[f][1], p[dw + 2], wv);
            }
        }
    }

    // ---- epilogue in regs, stage to smem ----
    {
        int gc = cg * MC4 + cl;
        float bS = sb[gc];
        float b0 = eb[e0  * Cc + gc];
        float b1 = eb[e1i * Cc + gc];

        float aS0,aS1,aS2,aS3, a00,a01,a02,a03, a10,a11,a12,a13;
        upk(acc[0][0], aS0, aS1); upk(acc[0][1], aS2, aS3);
        upk(acc[1][0], a00, a01); upk(acc[1][1], a02, a03);
        upk(acc[2][0], a10, a11); upk(acc[2][1], a12, a13);

        float4 res;
        {
            float ea = __expf(a00 + b0), ebv = __expf(a10 + b1);
            float cm = ea + w1 * ebv; cm = (cm == 0.f) ? EPSV : cm;
            res.x = __logf(cm) + aS0 + bS;
        }
        {
            float ea = __expf(a01 + b0), ebv = __expf(a11 + b1);
            float cm = ea + w1 * ebv; cm = (cm == 0.f) ? EPSV : cm;
            res.y = __logf(cm) + aS1 + bS;
        }
        {
            float ea = __expf(a02 + b0), ebv = __expf(a12 + b1);
            float cm = ea + w1 * ebv; cm = (cm == 0.f) ? EPSV : cm;
            res.z = __logf(cm) + aS2 + bS;
        }
        {
            float ea = __expf(a03 + b0), ebv = __expf(a13 + b1);
            float cm = ea + w1 * ebv; cm = (cm == 0.f) ? EPSV : cm;
            res.w = __logf(cm) + aS3 + bS;
        }
        *reinterpret_cast<float4*>(sOut + (cl * 2 + r) * 128 + qx * 4) = res;
    }
    __syncthreads();

    // ---- c-fastest store: STG.128 of 4 channels per px ----
    {
        long long obase = ((long long)b * HWp + h0 * Ww) * Cc + cg * MC4;
        int row = t >> 7;            // 0..1
        int px  = t & 127;
        float4 v;
        v.x = sOut[(0 * 2 + row) * 128 + px];
        v.y = sOut[(1 * 2 + row) * 128 + px];
        v.z = sOut[(2 * 2 + row) * 128 + px];
        v.w = sOut[(3 * 2 + row) * 128 + px];
        *reinterpret_cast<float4*>(out + obase + (long long)(row * Ww + px) * Cc) = v;
    }
}

// ============================================================
extern "C" void kernel_launch(void* const* d_in, const int* in_sizes, int n_in,
                              void* d_out, int out_size) {
    const float* x  = (const float*)d_in[0];
    const float* rw = (const float*)d_in[1];
    const float* rb = (const float*)d_in[2];
    const float* wg = (const float*)d_in[3];
    const float* ew = (const float*)d_in[4];
    const float* eb = (const float*)d_in[5];
    const float* sw = (const float*)d_in[6];
    const float* sb = (const float*)d_in[7];
    float* out = (float*)d_out;

    router_kernel<<<dim3(Bz, NBAND, RCG), 256>>>(x, rw, rb, wg);
    gate_kernel<<<1, 32>>>(out, (long long)out_size - 1);
    main_kernel<<<dim3(Hh / 2, Cc / MC4, Bz), 256>>>(x, ew, eb, sw, sb, out);
}

// round 12
// speedup vs baseline: 1.2875x; 1.2875x over previous
#include <cuda_runtime.h>
#include <math.h>

#define Bz 16
#define Cc 64
#define Hh 128
#define Ww 128
#define HWp (Hh*Ww)
#define EPSV 2.220446049250313e-16f
#define NBAND 16
#define RCG 4            // router channel groups
#define RCH 16

// ---- device scratch ----
__device__ float g_part[Bz * NBAND * RCG * 8];
__device__ int   g_sel[Bz * 2];
__device__ float g_w1[Bz];

typedef unsigned long long u64;

__device__ __forceinline__ u64 pk(float lo, float hi) {
    u64 r; asm("mov.b64 %0, {%1,%2};" : "=l"(r) : "f"(lo), "f"(hi)); return r;
}
__device__ __forceinline__ void upk(u64 v, float& lo, float& hi) {
    asm("mov.b64 {%0,%1}, %2;" : "=f"(lo), "=f"(hi) : "l"(v));
}
__device__ __forceinline__ void fma2(u64& d, u64 a, u64 b) {
    asm("fma.rn.f32x2 %0, %1, %2, %0;" : "+l"(d) : "l"(a), "l"(b));
}

// ============================================================
// Router (measured 83.7us, unchanged): conv7x7 partial over 16 channels
// + logit partials. grid (Bz, NBAND, RCG), block 256. 8-row bands,
// double-buffered channel tiles.
// ============================================================
#define RT_ROWS 14
#define RT_COLS 136
#define RT_ELEM (RT_ROWS * RT_COLS)   // 1904

__global__ __launch_bounds__(256) void router_kernel(
    const float* __restrict__ x,   // [B,C,H,W]
    const float* __restrict__ rw,  // [1,C,7,7]
    const float* __restrict__ rb,  // [1]
    const float* __restrict__ wg)  // [HW, E]
{
    __shared__ float sW[RCH * 49];
    __shared__ __align__(16) float sT[2][RT_ELEM];
    __shared__ float sPart[8][8];

    int b    = blockIdx.x;
    int band = blockIdx.y;
    int cg   = blockIdx.z;
    int h0   = band * 8;
    int t    = threadIdx.x;
    int row  = t >> 5;      // 0..7
    int wq   = t & 31;
    int ws   = wq * 4;

    for (int i = t; i < RCH * 49; i += 256)
        sW[i] = rw[cg * RCH * 49 + i];

    const float* xb = x + ((long long)b * Cc + cg * RCH) * HWp;

    float pf[8];
    #pragma unroll
    for (int k = 0; k < 8; ++k) {
        int idx = t + k * 256;
        float v = 0.f;
        if (idx < RT_ELEM) {
            int rr  = idx / RT_COLS;
            int col = idx - rr * RT_COLS;
            int gh = h0 - 3 + rr;
            int gw = col - 3;
            if (col < 134 && gh >= 0 && gh < Hh && gw >= 0 && gw < Ww)
                v = xb[gh * Ww + gw];
        }
        pf[k] = v;
    }

    u64 acc01 = pk(0.f, 0.f);
    u64 acc23 = pk(0.f, 0.f);

    for (int c = 0; c < RCH; ++c) {
        int buf = c & 1;
        #pragma unroll
        for (int k = 0; k < 8; ++k) {
            int idx = t + k * 256;
            if (idx < RT_ELEM) sT[buf][idx] = pf[k];
        }
        __syncthreads();
        if (c + 1 < RCH) {
            const float* xc = xb + (long long)(c + 1) * HWp;
            #pragma unroll
            for (int k = 0; k < 8; ++k) {
                int idx = t + k * 256;
                float v = 0.f;
                if (idx < RT_ELEM) {
                    int rr  = idx / RT_COLS;
                    int col = idx - rr * RT_COLS;
                    int gh = h0 - 3 + rr;
                    int gw = col - 3;
                    if (col < 134 && gh >= 0 && gh < Hh && gw >= 0 && gw < Ww)
                        v = xc[gh * Ww + gw];
                }
                pf[k] = v;
            }
        }
        const float* tb = sT[buf];
        const float* wc = sW + c * 49;
        #pragma unroll
        for (int dh = 0; dh < 7; ++dh) {
            u64 w7[7];
            #pragma unroll
            for (int dw = 0; dw < 7; ++dw) {
                float w = wc[dh * 7 + dw];
                w7[dw] = pk(w, w);
            }
            const float* rp = tb + (row + dh) * RT_COLS + ws;
            float4 v0 = *reinterpret_cast<const float4*>(rp);
            float4 v1 = *reinterpret_cast<const float4*>(rp + 4);
            float2 v2 = *reinterpret_cast<const float2*>(rp + 8);
            float tt[10];
            tt[0]=v0.x; tt[1]=v0.y; tt[2]=v0.z; tt[3]=v0.w;
            tt[4]=v1.x; tt[5]=v1.y; tt[6]=v1.z; tt[7]=v1.w;
            tt[8]=v2.x; tt[9]=v2.y;
            u64 p[9];
            #pragma unroll
            for (int j = 0; j < 9; ++j) p[j] = pk(tt[j], tt[j+1]);
            #pragma unroll
            for (int dw = 0; dw < 7; ++dw) {
                fma2(acc01, p[dw],     w7[dw]);
                fma2(acc23, p[dw + 2], w7[dw]);
            }
        }
    }

    float rbv = (cg == 0) ? rb[0] : 0.f;
    float rv[4];
    upk(acc01, rv[0], rv[1]);
    upk(acc23, rv[2], rv[3]);
    #pragma unroll
    for (int px = 0; px < 4; ++px) rv[px] += rbv;

    float lacc[8];
    #pragma unroll
    for (int e = 0; e < 8; ++e) lacc[e] = 0.f;
    int h = h0 + row;
    #pragma unroll
    for (int px = 0; px < 4; ++px) {
        int p = h * Ww + ws + px;
        const float4* wp = reinterpret_cast<const float4*>(wg + (long long)p * 8);
        float4 a  = wp[0];
        float4 bb = wp[1];
        float r = rv[px];
        lacc[0] += r * a.x;  lacc[1] += r * a.y;  lacc[2] += r * a.z;  lacc[3] += r * a.w;
        lacc[4] += r * bb.x; lacc[5] += r * bb.y; lacc[6] += r * bb.z; lacc[7] += r * bb.w;
    }

    int lane = t & 31, warp = t >> 5;
    #pragma unroll
    for (int e = 0; e < 8; ++e) {
        float v = lacc[e];
        #pragma unroll
        for (int off = 16; off; off >>= 1) v += __shfl_down_sync(0xffffffffu, v, off);
        if (lane == 0) sPart[warp][e] = v;
    }
    __syncthreads();
    if (t < 8) {
        float s = 0.f;
        #pragma unroll
        for (int w2 = 0; w2 < 8; ++w2) s += sPart[w2][t];
        g_part[(((b * NBAND) + band) * RCG + cg) * 8 + t] = s;
    }
}

// ============================================================
// Gating: logits -> top-2 -> gates, deterministic loss.
// ============================================================
__global__ void gate_kernel(float* __restrict__ out, long long loss_idx)
{
    __shared__ float sg0[Bz], sg1[Bz];
    __shared__ int   si0[Bz], si1[Bz];
    int t = threadIdx.x;

    if (t < Bz) {
        float l[8];
        #pragma unroll
        for (int e = 0; e < 8; ++e) {
            float s = 0.f;
            for (int k = 0; k < NBAND * RCG; ++k)
                s += g_part[(t * NBAND * RCG + k) * 8 + e];
            l[e] = s;
        }
        int i0 = 0; float m0 = l[0];
        #pragma unroll
        for (int e = 1; e < 8; ++e) if (l[e] > m0) { m0 = l[e]; i0 = e; }
        int i1 = (i0 == 0) ? 1 : 0; float m1 = l[i1];
        #pragma unroll
        for (int e = 0; e < 8; ++e)
            if (e != i0 && l[e] > m1) { m1 = l[e]; i1 = e; }
        float ex = expf(m1 - m0);
        float g0 = 1.f / (1.f + ex);
        float g1 = ex / (1.f + ex);
        g_sel[t * 2]     = i0;
        g_sel[t * 2 + 1] = i1;
        g_w1[t] = (g1 > 0.f) ? 1.f : 0.f;
        si0[t] = i0; si1[t] = i1; sg0[t] = g0; sg1[t] = g1;
    }
    __syncthreads();
    if (t == 0) {
        float imp[8]; float ldc[8];
        #pragma unroll
        for (int e = 0; e < 8; ++e) { imp[e] = 0.f; ldc[e] = 0.f; }
        for (int bb = 0; bb < Bz; ++bb) {
            imp[si0[bb]] += sg0[bb];
            imp[si1[bb]] += sg1[bb];
            ldc[si0[bb]] += 1.f;
            if (sg1[bb] > 0.f) ldc[si1[bb]] += 1.f;
        }
        float mi = 0.f, ml = 0.f;
        for (int e = 0; e < 8; ++e) { mi += imp[e]; ml += ldc[e]; }
        mi *= 0.125f; ml *= 0.125f;
        float vi = 0.f, vl = 0.f;
        for (int e = 0; e < 8; ++e) {
            float d  = imp[e] - mi; vi += d * d;
            float dl = ldc[e] - ml; vl += dl * dl;
        }
        vi *= (1.f / 7.f); vl *= (1.f / 7.f);
        float loss = (vi / (mi * mi + 1e-10f) + vl / (ml * ml + 1e-10f)) * 0.01f;
        out[loss_idx] = loss;
    }
}

// ============================================================
// Main fused kernel v6: v4 tiling (4 ch, 4-row strips, same grid/traffic)
// but 8 px/lane. Warp = (channel, row-pair): lanes 0-15 row 2rp, lanes
// 16-31 row 2rp+1, 8 px per lane. No serial channel loop.
// Per dh: 4 tap loads + 13 pk + 21 weight LDS.64 -> 84 fma2 (1:4 ratio).
// ============================================================
#define MC4 4                    // channels per block
#define MROW 10                  // tile rows (4 + 6 halo)
#define MCOL 136                 // 134 used
#define MTILE (MC4 * MROW * MCOL) // 5440 words

__global__ __launch_bounds__(256, 3) void main_kernel(
    const float* __restrict__ x,    // [B,C,H,W]
    const float* __restrict__ ew,   // [E,C,1,7,7]
    const float* __restrict__ eb,   // [E,C]
    const float* __restrict__ sw,   // [C,1,7,7]
    const float* __restrict__ sb,   // [C]
    float* __restrict__ out)        // [B,HW,C]
{
    __shared__ __align__(16) float  sIn[MTILE];            // 21760 B
    __shared__ __align__(8)  float2 sWd[3 * MC4 * 49];     // 4704 B
    __shared__ __align__(16) float  sOut[MC4 * 4 * 128];   // 8192 B [cl][row][px]

    int hb = blockIdx.x;          // h-strip (4 rows)
    int cg = blockIdx.y;          // channel group (4 ch)
    int b  = blockIdx.z;
    int h0 = hb * 4;
    int t  = threadIdx.x;
    int w  = t >> 5;              // warp 0..7
    int cl = w >> 1;              // local channel 0..3
    int rp = w & 1;               // row pair 0..1
    int half = (t >> 4) & 1;      // row within pair
    int li   = t & 15;            // px octet index
    int row  = rp * 2 + half;     // output row in strip 0..3
    int px0  = li * 8;

    int e0  = g_sel[b * 2];
    int e1i = g_sel[b * 2 + 1];
    float w1 = g_w1[b];

    const float* xb = x + ((long long)b * Cc + cg * MC4) * HWp;

    // ---- load tile: 4 ch x 10 rows x 134 cols (col = gw + 3) ----
    for (int idx = t; idx < MTILE; idx += 256) {
        int c   = idx / (MROW * MCOL);
        int rem = idx - c * (MROW * MCOL);
        int rr  = rem / MCOL;
        int col = rem - rr * MCOL;
        int gh = h0 - 3 + rr;
        int gw = col - 3;
        float v = 0.f;
        if (gh >= 0 && gh < Hh && gw >= 0 && gw < Ww)
            v = xb[c * HWp + gh * Ww + gw];
        sIn[idx] = v;
    }
    // ---- duplicated weights [f][cl][49] as float2 ----
    for (int idx = t; idx < 3 * MC4 * 49; idx += 256) {
        int f   = idx / (MC4 * 49);
        int rem = idx - f * (MC4 * 49);
        int c2  = rem / 49;
        int k   = rem - c2 * 49;
        int gc  = cg * MC4 + c2;
        float wv = (f == 0) ? sw[gc * 49 + k]
                 : (f == 1) ? ew[e0  * (Cc * 49) + gc * 49 + k]
                            : ew[e1i * (Cc * 49) + gc * 49 + k];
        sWd[idx] = make_float2(wv, wv);
    }
    __syncthreads();

    // ---- compute: one (channel, row) per half-warp, 8 px per lane ----
    const float* inc = sIn + cl * (MROW * MCOL) + px0;
    const u64* wB = reinterpret_cast<const u64*>(sWd) + cl * 49;

    u64 acc[3][4];
    u64 z = pk(0.f, 0.f);
    #pragma unroll
    for (int f = 0; f < 3; ++f)
        #pragma unroll
        for (int q = 0; q < 4; ++q) acc[f][q] = z;

    #pragma unroll
    for (int dh = 0; dh < 7; ++dh) {
        const float* rpnt = inc + (row + dh) * MCOL;
        float4 v0 = *reinterpret_cast<const float4*>(rpnt);
        float4 v1 = *reinterpret_cast<const float4*>(rpnt + 4);
        float4 v2 = *reinterpret_cast<const float4*>(rpnt + 8);
        float2 v3 = *reinterpret_cast<const float2*>(rpnt + 12);
        float tt[14];
        tt[0]=v0.x;  tt[1]=v0.y;  tt[2]=v0.z;  tt[3]=v0.w;
        tt[4]=v1.x;  tt[5]=v1.y;  tt[6]=v1.z;  tt[7]=v1.w;
        tt[8]=v2.x;  tt[9]=v2.y;  tt[10]=v2.z; tt[11]=v2.w;
        tt[12]=v3.x; tt[13]=v3.y;
        u64 p[13];
        #pragma unroll
        for (int j = 0; j < 13; ++j) p[j] = pk(tt[j], tt[j+1]);
        #pragma unroll
        for (int f = 0; f < 3; ++f) {
            const u64* wf = wB + f * (MC4 * 49) + dh * 7;
            #pragma unroll
            for (int dw = 0; dw < 7; ++dw) {
                u64 wv = wf[dw];                 // LDS.64 broadcast
                fma2(acc[f][0], p[dw],     wv);
                fma2(acc[f][1], p[dw + 2], wv);
                fma2(acc[f][2], p[dw + 4], wv);
                fma2(acc[f][3], p[dw + 6], wv);
            }
        }
    }

    // ---- epilogue: 8 px, stage to smem ----
    {
        int gc = cg * MC4 + cl;
        float bS = sb[gc];
        float b0 = eb[e0  * Cc + gc];
        float b1 = eb[e1i * Cc + gc];

        float aS[8], a0[8], a1[8];
        #pragma unroll
        for (int q = 0; q < 4; ++q) {
            upk(acc[0][q], aS[2*q], aS[2*q+1]);
            upk(acc[1][q], a0[2*q], a0[2*q+1]);
            upk(acc[2][q], a1[2*q], a1[2*q+1]);
        }
        float res[8];
        #pragma unroll
        for (int j = 0; j < 8; ++j) {
            float ea = __expf(a0[j] + b0), ebv = __expf(a1[j] + b1);
            float cm = ea + w1 * ebv; cm = (cm == 0.f) ? EPSV : cm;
            res[j] = __logf(cm) + aS[j] + bS;
        }
        float* so = sOut + (cl * 4 + row) * 128 + px0;
        *reinterpret_cast<float4*>(so)     = make_float4(res[0], res[1], res[2], res[3]);
        *reinterpret_cast<float4*>(so + 4) = make_float4(res[4], res[5], res[6], res[7]);
    }
    __syncthreads();

    // ---- c-fastest store: STG.128 of 4 channels per px ----
    long long obase = ((long long)b * HWp + h0 * Ww) * Cc + cg * MC4;
    #pragma unroll
    for (int k = 0; k < 2; ++k) {
        int e    = t + k * 256;       // 0..511 = (row, px)
        int row2 = e >> 7;            // 0..3
        int px   = e & 127;
        float4 v;
        v.x = sOut[(0 * 4 + row2) * 128 + px];
        v.y = sOut[(1 * 4 + row2) * 128 + px];
        v.z = sOut[(2 * 4 + row2) * 128 + px];
        v.w = sOut[(3 * 4 + row2) * 128 + px];
        *reinterpret_cast<float4*>(out + obase + (long long)(row2 * Ww + px) * Cc) = v;
    }
}

// ============================================================
extern "C" void kernel_launch(void* const* d_in, const int* in_sizes, int n_in,
                              void* d_out, int out_size) {
    const float* x  = (const float*)d_in[0];
    const float* rw = (const float*)d_in[1];
    const float* rb = (const float*)d_in[2];
    const float* wg = (const float*)d_in[3];
    const float* ew = (const float*)d_in[4];
    const float* eb = (const float*)d_in[5];
    const float* sw = (const float*)d_in[6];
    const float* sb = (const float*)d_in[7];
    float* out = (float*)d_out;

    router_kernel<<<dim3(Bz, NBAND, RCG), 256>>>(x, rw, rb, wg);
    gate_kernel<<<1, 32>>>(out, (long long)out_size - 1);
    main_kernel<<<dim3(Hh / 4, Cc / MC4, Bz), 256>>>(x, ew, eb, sw, sb, out);
}

// round 13
// speedup vs baseline: 1.3366x; 1.0381x over previous
#include <cuda_runtime.h>
#include <math.h>

#define Bz 16
#define Cc 64
#define Hh 128
#define Ww 128
#define HWp (Hh*Ww)
#define EPSV 2.220446049250313e-16f
#define NBAND 16
#define RCG 4            // router channel groups
#define RCH 16

// ---- device scratch ----
__device__ float g_part[Bz * NBAND * RCG * 8];
__device__ int   g_sel[Bz * 2];
__device__ float g_w1[Bz];

typedef unsigned long long u64;

__device__ __forceinline__ u64 pk(float lo, float hi) {
    u64 r; asm("mov.b64 %0, {%1,%2};" : "=l"(r) : "f"(lo), "f"(hi)); return r;
}
__device__ __forceinline__ void upk(u64 v, float& lo, float& hi) {
    asm("mov.b64 {%0,%1}, %2;" : "=f"(lo), "=f"(hi) : "l"(v));
}
__device__ __forceinline__ void fma2(u64& d, u64 a, u64 b) {
    asm("fma.rn.f32x2 %0, %1, %2, %0;" : "+l"(d) : "l"(a), "l"(b));
}

// ============================================================
// Router (measured 83.7us, unchanged control): conv7x7 partial over 16
// channels + logit partials. grid (Bz, NBAND, RCG), block 256.
// ============================================================
#define RT_ROWS 14
#define RT_COLS 136
#define RT_ELEM (RT_ROWS * RT_COLS)   // 1904

__global__ __launch_bounds__(256) void router_kernel(
    const float* __restrict__ x,   // [B,C,H,W]
    const float* __restrict__ rw,  // [1,C,7,7]
    const float* __restrict__ rb,  // [1]
    const float* __restrict__ wg)  // [HW, E]
{
    __shared__ float sW[RCH * 49];
    __shared__ __align__(16) float sT[2][RT_ELEM];
    __shared__ float sPart[8][8];

    int b    = blockIdx.x;
    int band = blockIdx.y;
    int cg   = blockIdx.z;
    int h0   = band * 8;
    int t    = threadIdx.x;
    int row  = t >> 5;      // 0..7
    int wq   = t & 31;
    int ws   = wq * 4;

    for (int i = t; i < RCH * 49; i += 256)
        sW[i] = rw[cg * RCH * 49 + i];

    const float* xb = x + ((long long)b * Cc + cg * RCH) * HWp;

    float pf[8];
    #pragma unroll
    for (int k = 0; k < 8; ++k) {
        int idx = t + k * 256;
        float v = 0.f;
        if (idx < RT_ELEM) {
            int rr  = idx / RT_COLS;
            int col = idx - rr * RT_COLS;
            int gh = h0 - 3 + rr;
            int gw = col - 3;
            if (col < 134 && gh >= 0 && gh < Hh && gw >= 0 && gw < Ww)
                v = xb[gh * Ww + gw];
        }
        pf[k] = v;
    }

    u64 acc01 = pk(0.f, 0.f);
    u64 acc23 = pk(0.f, 0.f);

    for (int c = 0; c < RCH; ++c) {
        int buf = c & 1;
        #pragma unroll
        for (int k = 0; k < 8; ++k) {
            int idx = t + k * 256;
            if (idx < RT_ELEM) sT[buf][idx] = pf[k];
        }
        __syncthreads();
        if (c + 1 < RCH) {
            const float* xc = xb + (long long)(c + 1) * HWp;
            #pragma unroll
            for (int k = 0; k < 8; ++k) {
                int idx = t + k * 256;
                float v = 0.f;
                if (idx < RT_ELEM) {
                    int rr  = idx / RT_COLS;
                    int col = idx - rr * RT_COLS;
                    int gh = h0 - 3 + rr;
                    int gw = col - 3;
                    if (col < 134 && gh >= 0 && gh < Hh && gw >= 0 && gw < Ww)
                        v = xc[gh * Ww + gw];
                }
                pf[k] = v;
            }
        }
        const float* tb = sT[buf];
        const float* wc = sW + c * 49;
        #pragma unroll
        for (int dh = 0; dh < 7; ++dh) {
            u64 w7[7];
            #pragma unroll
            for (int dw = 0; dw < 7; ++dw) {
                float w = wc[dh * 7 + dw];
                w7[dw] = pk(w, w);
            }
            const float* rp = tb + (row + dh) * RT_COLS + ws;
            float4 v0 = *reinterpret_cast<const float4*>(rp);
            float4 v1 = *reinterpret_cast<const float4*>(rp + 4);
            float2 v2 = *reinterpret_cast<const float2*>(rp + 8);
            float tt[10];
            tt[0]=v0.x; tt[1]=v0.y; tt[2]=v0.z; tt[3]=v0.w;
            tt[4]=v1.x; tt[5]=v1.y; tt[6]=v1.z; tt[7]=v1.w;
            tt[8]=v2.x; tt[9]=v2.y;
            u64 p[9];
            #pragma unroll
            for (int j = 0; j < 9; ++j) p[j] = pk(tt[j], tt[j+1]);
            #pragma unroll
            for (int dw = 0; dw < 7; ++dw) {
                fma2(acc01, p[dw],     w7[dw]);
                fma2(acc23, p[dw + 2], w7[dw]);
            }
        }
    }

    float rbv = (cg == 0) ? rb[0] : 0.f;
    float rv[4];
    upk(acc01, rv[0], rv[1]);
    upk(acc23, rv[2], rv[3]);
    #pragma unroll
    for (int px = 0; px < 4; ++px) rv[px] += rbv;

    float lacc[8];
    #pragma unroll
    for (int e = 0; e < 8; ++e) lacc[e] = 0.f;
    int h = h0 + row;
    #pragma unroll
    for (int px = 0; px < 4; ++px) {
        int p = h * Ww + ws + px;
        const float4* wp = reinterpret_cast<const float4*>(wg + (long long)p * 8);
        float4 a  = wp[0];
        float4 bb = wp[1];
        float r = rv[px];
        lacc[0] += r * a.x;  lacc[1] += r * a.y;  lacc[2] += r * a.z;  lacc[3] += r * a.w;
        lacc[4] += r * bb.x; lacc[5] += r * bb.y; lacc[6] += r * bb.z; lacc[7] += r * bb.w;
    }

    int lane = t & 31, warp = t >> 5;
    #pragma unroll
    for (int e = 0; e < 8; ++e) {
        float v = lacc[e];
        #pragma unroll
        for (int off = 16; off; off >>= 1) v += __shfl_down_sync(0xffffffffu, v, off);
        if (lane == 0) sPart[warp][e] = v;
    }
    __syncthreads();
    if (t < 8) {
        float s = 0.f;
        #pragma unroll
        for (int w2 = 0; w2 < 8; ++w2) s += sPart[w2][t];
        g_part[(((b * NBAND) + band) * RCG + cg) * 8 + t] = s;
    }
}

// ============================================================
// Gating: logits -> top-2 -> gates, deterministic loss.
// ============================================================
__global__ void gate_kernel(float* __restrict__ out, long long loss_idx)
{
    __shared__ float sg0[Bz], sg1[Bz];
    __shared__ int   si0[Bz], si1[Bz];
    int t = threadIdx.x;

    if (t < Bz) {
        float l[8];
        #pragma unroll
        for (int e = 0; e < 8; ++e) {
            float s = 0.f;
            for (int k = 0; k < NBAND * RCG; ++k)
                s += g_part[(t * NBAND * RCG + k) * 8 + e];
            l[e] = s;
        }
        int i0 = 0; float m0 = l[0];
        #pragma unroll
        for (int e = 1; e < 8; ++e) if (l[e] > m0) { m0 = l[e]; i0 = e; }
        int i1 = (i0 == 0) ? 1 : 0; float m1 = l[i1];
        #pragma unroll
        for (int e = 0; e < 8; ++e)
            if (e != i0 && l[e] > m1) { m1 = l[e]; i1 = e; }
        float ex = expf(m1 - m0);
        float g0 = 1.f / (1.f + ex);
        float g1 = ex / (1.f + ex);
        g_sel[t * 2]     = i0;
        g_sel[t * 2 + 1] = i1;
        g_w1[t] = (g1 > 0.f) ? 1.f : 0.f;
        si0[t] = i0; si1[t] = i1; sg0[t] = g0; sg1[t] = g1;
    }
    __syncthreads();
    if (t == 0) {
        float imp[8]; float ldc[8];
        #pragma unroll
        for (int e = 0; e < 8; ++e) { imp[e] = 0.f; ldc[e] = 0.f; }
        for (int bb = 0; bb < Bz; ++bb) {
            imp[si0[bb]] += sg0[bb];
            imp[si1[bb]] += sg1[bb];
            ldc[si0[bb]] += 1.f;
            if (sg1[bb] > 0.f) ldc[si1[bb]] += 1.f;
        }
        float mi = 0.f, ml = 0.f;
        for (int e = 0; e < 8; ++e) { mi += imp[e]; ml += ldc[e]; }
        mi *= 0.125f; ml *= 0.125f;
        float vi = 0.f, vl = 0.f;
        for (int e = 0; e < 8; ++e) {
            float d  = imp[e] - mi; vi += d * d;
            float dl = ldc[e] - ml; vl += dl * dl;
        }
        vi *= (1.f / 7.f); vl *= (1.f / 7.f);
        float loss = (vi / (mi * mi + 1e-10f) + vl / (ml * ml + 1e-10f)) * 0.01f;
        out[loss_idx] = loss;
    }
}

// ============================================================
// Main fused kernel v7: R7's v4 layout (best measured) + LSE epilogue
// (2 MUFU/px instead of 3 — attacks the MUFU pipe bound).
// 4 ch/block, 4-row strips, block 256 = 8 warps, warp = (row, ch-pair),
// serial 2-channel loop, 3 blocks/SM.
// ============================================================
#define MC4 4                    // channels per block
#define MROW 10                  // tile rows (4 + 6 halo)
#define MCOL 136                 // 134 used
#define MTILE (MC4 * MROW * MCOL) // 5440 words

__device__ __forceinline__ float lse_combine(float u, float v, float w1,
                                             float add) {
    // w1==1: log(e^u + e^v) = max + log(1 + exp(-|u-v|))   [2 MUFU]
    // w1==0: log(e^u) = u
    float M = fmaxf(u, v);
    float lse = M + __logf(1.0f + __expf(-fabsf(u - v)));
    return ((w1 > 0.f) ? lse : u) + add;
}

__global__ __launch_bounds__(256, 3) void main_kernel(
    const float* __restrict__ x,    // [B,C,H,W]
    const float* __restrict__ ew,   // [E,C,1,7,7]
    const float* __restrict__ eb,   // [E,C]
    const float* __restrict__ sw,   // [C,1,7,7]
    const float* __restrict__ sb,   // [C]
    float* __restrict__ out)        // [B,HW,C]
{
    __shared__ __align__(16) float  sIn[MTILE];            // 21760 B
    __shared__ __align__(8)  float2 sWd[3 * MC4 * 49];     // 4704 B
    __shared__ __align__(16) float  sOut[MC4 * 4 * 128];   // 8192 B [cl][row][px]

    int hb = blockIdx.x;          // h-strip
    int cg = blockIdx.y;          // channel group (4 ch)
    int b  = blockIdx.z;
    int h0 = hb * 4;
    int t  = threadIdx.x;
    int w  = t >> 5;              // warp 0..7
    int qx = t & 31;              // px-quad
    int r  = w & 3;               // output row in strip
    int cp = w >> 2;              // channel pair 0..1

    int e0  = g_sel[b * 2];
    int e1i = g_sel[b * 2 + 1];
    float w1 = g_w1[b];

    const float* xb = x + ((long long)b * Cc + cg * MC4) * HWp;

    // ---- load tile: 4 ch x 10 rows x 134 cols ----
    for (int idx = t; idx < MTILE; idx += 256) {
        int c   = idx / (MROW * MCOL);
        int rem = idx - c * (MROW * MCOL);
        int rr  = rem / MCOL;
        int col = rem - rr * MCOL;
        int gh = h0 - 3 + rr;
        int gw = col - 3;
        float v = 0.f;
        if (gh >= 0 && gh < Hh && gw >= 0 && gw < Ww)
            v = xb[c * HWp + gh * Ww + gw];
        sIn[idx] = v;
    }
    // ---- duplicated weights [f][cl][49] as float2 ----
    for (int idx = t; idx < 3 * MC4 * 49; idx += 256) {
        int f   = idx / (MC4 * 49);
        int rem = idx - f * (MC4 * 49);
        int cl  = rem / 49;
        int k   = rem - cl * 49;
        int gc  = cg * MC4 + cl;
        float wv = (f == 0) ? sw[gc * 49 + k]
                 : (f == 1) ? ew[e0  * (Cc * 49) + gc * 49 + k]
                            : ew[e1i * (Cc * 49) + gc * 49 + k];
        sWd[idx] = make_float2(wv, wv);
    }
    __syncthreads();

    // ---- compute: loop 2 channels of this warp's pair ----
    #pragma unroll
    for (int ci = 0; ci < 2; ++ci) {
        int cl = cp * 2 + ci;                 // local channel 0..3
        const float* inc = sIn + cl * (MROW * MCOL) + qx * 4;
        const u64* wB = reinterpret_cast<const u64*>(sWd) + cl * 49;

        u64 acc[3][2];
        u64 z = pk(0.f, 0.f);
        #pragma unroll
        for (int f = 0; f < 3; ++f) { acc[f][0] = z; acc[f][1] = z; }

        #pragma unroll
        for (int dh = 0; dh < 7; ++dh) {
            const float* rp = inc + (r + dh) * MCOL;
            float4 v0 = *reinterpret_cast<const float4*>(rp);
            float4 v1 = *reinterpret_cast<const float4*>(rp + 4);
            float2 v2 = *reinterpret_cast<const float2*>(rp + 8);
            float tt[10];
            tt[0]=v0.x; tt[1]=v0.y; tt[2]=v0.z; tt[3]=v0.w;
            tt[4]=v1.x; tt[5]=v1.y; tt[6]=v1.z; tt[7]=v1.w;
            tt[8]=v2.x; tt[9]=v2.y;
            u64 p[9];
            #pragma unroll
            for (int j = 0; j < 9; ++j) p[j] = pk(tt[j], tt[j+1]);
            #pragma unroll
            for (int f = 0; f < 3; ++f) {
                const u64* wf = wB + f * (MC4 * 49) + dh * 7;
                #pragma unroll
                for (int dw = 0; dw < 7; ++dw) {
                    u64 wv = wf[dw];                 // LDS.64 broadcast
                    fma2(acc[f][0], p[dw],     wv);
                    fma2(acc[f][1], p[dw + 2], wv);
                }
            }
        }

        // ---- LSE epilogue (2 MUFU/px), stage to smem ----
        int gc = cg * MC4 + cl;
        float bS = sb[gc];
        float b0 = eb[e0  * Cc + gc];
        float b1 = eb[e1i * Cc + gc];

        float aS0,aS1,aS2,aS3, a00,a01,a02,a03, a10,a11,a12,a13;
        upk(acc[0][0], aS0, aS1); upk(acc[0][1], aS2, aS3);
        upk(acc[1][0], a00, a01); upk(acc[1][1], a02, a03);
        upk(acc[2][0], a10, a11); upk(acc[2][1], a12, a13);

        float4 res;
        res.x = lse_combine(a00 + b0, a10 + b1, w1, aS0 + bS);
        res.y = lse_combine(a01 + b0, a11 + b1, w1, aS1 + bS);
        res.z = lse_combine(a02 + b0, a12 + b1, w1, aS2 + bS);
        res.w = lse_combine(a03 + b0, a13 + b1, w1, aS3 + bS);
        *reinterpret_cast<float4*>(sOut + (cl * 4 + r) * 128 + qx * 4) = res;
    }
    __syncthreads();

    // ---- c-fastest store: STG.128 of 4 channels per px ----
    long long obase = ((long long)b * HWp + h0 * Ww) * Cc + cg * MC4;
    #pragma unroll
    for (int k = 0; k < 2; ++k) {
        int e   = t + k * 256;        // 0..511 = (row, px)
        int row = e >> 7;
        int px  = e & 127;
        float4 v;
        v.x = sOut[(0 * 4 + row) * 128 + px];
        v.y = sOut[(1 * 4 + row) * 128 + px];
        v.z = sOut[(2 * 4 + row) * 128 + px];
        v.w = sOut[(3 * 4 + row) * 128 + px];
        *reinterpret_cast<float4*>(out + obase + (long long)(row * Ww + px) * Cc) = v;
    }
}

// ============================================================
extern "C" void kernel_launch(void* const* d_in, const int* in_sizes, int n_in,
                              void* d_out, int out_size) {
    const float* x  = (const float*)d_in[0];
    const float* rw = (const float*)d_in[1];
    const float* rb = (const float*)d_in[2];
    const float* wg = (const float*)d_in[3];
    const float* ew = (const float*)d_in[4];
    const float* eb = (const float*)d_in[5];
    const float* sw = (const float*)d_in[6];
    const float* sb = (const float*)d_in[7];
    float* out = (float*)d_out;

    router_kernel<<<dim3(Bz, NBAND, RCG), 256>>>(x, rw, rb, wg);
    gate_kernel<<<1, 32>>>(out, (long long)out_size - 1);
    main_kernel<<<dim3(Hh / 4, Cc / MC4, Bz), 256>>>(x, ew, eb, sw, sb, out);
}

// round 15
// speedup vs baseline: 1.4701x; 1.0999x over previous
#include <cuda_runtime.h>
#include <math.h>

#define Bz 16
#define Cc 64
#define Hh 128
#define Ww 128
#define HWp (Hh*Ww)
#define EPSV 2.220446049250313e-16f
#define NBAND 16
#define RCG 4            // router channel groups
#define RCH 16

// ---- device scratch ----
__device__ float g_part[Bz * NBAND * RCG * 8];
__device__ int   g_sel[Bz * 2];
__device__ float g_w1[Bz];

typedef unsigned long long u64;

__device__ __forceinline__ u64 pk(float lo, float hi) {
    u64 r; asm("mov.b64 %0, {%1,%2};" : "=l"(r) : "f"(lo), "f"(hi)); return r;
}
__device__ __forceinline__ void upk(u64 v, float& lo, float& hi) {
    asm("mov.b64 {%0,%1}, %2;" : "=f"(lo), "=f"(hi) : "l"(v));
}
__device__ __forceinline__ void fma2(u64& d, u64 a, u64 b) {
    asm("fma.rn.f32x2 %0, %1, %2, %0;" : "+l"(d) : "l"(a), "l"(b));
}

// ============================================================
// Router (measured 83.7us, unchanged control): conv7x7 partial over 16
// channels + logit partials. grid (Bz, NBAND, RCG), block 256.
// ============================================================
#define RT_ROWS 14
#define RT_COLS 136
#define RT_ELEM (RT_ROWS * RT_COLS)   // 1904

__global__ __launch_bounds__(256) void router_kernel(
    const float* __restrict__ x,   // [B,C,H,W]
    const float* __restrict__ rw,  // [1,C,7,7]
    const float* __restrict__ rb,  // [1]
    const float* __restrict__ wg)  // [HW, E]
{
    __shared__ float sW[RCH * 49];
    __shared__ __align__(16) float sT[2][RT_ELEM];
    __shared__ float sPart[8][8];

    int b    = blockIdx.x;
    int band = blockIdx.y;
    int cg   = blockIdx.z;
    int h0   = band * 8;
    int t    = threadIdx.x;
    int row  = t >> 5;      // 0..7
    int wq   = t & 31;
    int ws   = wq * 4;

    for (int i = t; i < RCH * 49; i += 256)
        sW[i] = rw[cg * RCH * 49 + i];

    const float* xb = x + ((long long)b * Cc + cg * RCH) * HWp;

    float pf[8];
    #pragma unroll
    for (int k = 0; k < 8; ++k) {
        int idx = t + k * 256;
        float v = 0.f;
        if (idx < RT_ELEM) {
            int rr  = idx / RT_COLS;
            int col = idx - rr * RT_COLS;
            int gh = h0 - 3 + rr;
            int gw = col - 3;
            if (col < 134 && gh >= 0 && gh < Hh && gw >= 0 && gw < Ww)
                v = xb[gh * Ww + gw];
        }
        pf[k] = v;
    }

    u64 acc01 = pk(0.f, 0.f);
    u64 acc23 = pk(0.f, 0.f);

    for (int c = 0; c < RCH; ++c) {
        int buf = c & 1;
        #pragma unroll
        for (int k = 0; k < 8; ++k) {
            int idx = t + k * 256;
            if (idx < RT_ELEM) sT[buf][idx] = pf[k];
        }
        __syncthreads();
        if (c + 1 < RCH) {
            const float* xc = xb + (long long)(c + 1) * HWp;
            #pragma unroll
            for (int k = 0; k < 8; ++k) {
                int idx = t + k * 256;
                float v = 0.f;
                if (idx < RT_ELEM) {
                    int rr  = idx / RT_COLS;
                    int col = idx - rr * RT_COLS;
                    int gh = h0 - 3 + rr;
                    int gw = col - 3;
                    if (col < 134 && gh >= 0 && gh < Hh && gw >= 0 && gw < Ww)
                        v = xc[gh * Ww + gw];
                }
                pf[k] = v;
            }
        }
        const float* tb = sT[buf];
        const float* wc = sW + c * 49;
        #pragma unroll
        for (int dh = 0; dh < 7; ++dh) {
            u64 w7[7];
            #pragma unroll
            for (int dw = 0; dw < 7; ++dw) {
                float w = wc[dh * 7 + dw];
                w7[dw] = pk(w, w);
            }
            const float* rp = tb + (row + dh) * RT_COLS + ws;
            float4 v0 = *reinterpret_cast<const float4*>(rp);
            float4 v1 = *reinterpret_cast<const float4*>(rp + 4);
            float2 v2 = *reinterpret_cast<const float2*>(rp + 8);
            float tt[10];
            tt[0]=v0.x; tt[1]=v0.y; tt[2]=v0.z; tt[3]=v0.w;
            tt[4]=v1.x; tt[5]=v1.y; tt[6]=v1.z; tt[7]=v1.w;
            tt[8]=v2.x; tt[9]=v2.y;
            u64 p[9];
            #pragma unroll
            for (int j = 0; j < 9; ++j) p[j] = pk(tt[j], tt[j+1]);
            #pragma unroll
            for (int dw = 0; dw < 7; ++dw) {
                fma2(acc01, p[dw],     w7[dw]);
                fma2(acc23, p[dw + 2], w7[dw]);
            }
        }
    }

    float rbv = (cg == 0) ? rb[0] : 0.f;
    float rv[4];
    upk(acc01, rv[0], rv[1]);
    upk(acc23, rv[2], rv[3]);
    #pragma unroll
    for (int px = 0; px < 4; ++px) rv[px] += rbv;

    float lacc[8];
    #pragma unroll
    for (int e = 0; e < 8; ++e) lacc[e] = 0.f;
    int h = h0 + row;
    #pragma unroll
    for (int px = 0; px < 4; ++px) {
        int p = h * Ww + ws + px;
        const float4* wp = reinterpret_cast<const float4*>(wg + (long long)p * 8);
        float4 a  = wp[0];
        float4 bb = wp[1];
        float r = rv[px];
        lacc[0] += r * a.x;  lacc[1] += r * a.y;  lacc[2] += r * a.z;  lacc[3] += r * a.w;
        lacc[4] += r * bb.x; lacc[5] += r * bb.y; lacc[6] += r * bb.z; lacc[7] += r * bb.w;
    }

    int lane = t & 31, warp = t >> 5;
    #pragma unroll
    for (int e = 0; e < 8; ++e) {
        float v = lacc[e];
        #pragma unroll
        for (int off = 16; off; off >>= 1) v += __shfl_down_sync(0xffffffffu, v, off);
        if (lane == 0) sPart[warp][e] = v;
    }
    __syncthreads();
    if (t < 8) {
        float s = 0.f;
        #pragma unroll
        for (int w2 = 0; w2 < 8; ++w2) s += sPart[w2][t];
        g_part[(((b * NBAND) + band) * RCG + cg) * 8 + t] = s;
    }
}

// ============================================================
// Gating: logits -> top-2 -> gates, deterministic loss.
// ============================================================
__global__ void gate_kernel(float* __restrict__ out, long long loss_idx)
{
    __shared__ float sg0[Bz], sg1[Bz];
    __shared__ int   si0[Bz], si1[Bz];
    int t = threadIdx.x;

    if (t < Bz) {
        float l[8];
        #pragma unroll
        for (int e = 0; e < 8; ++e) {
            float s = 0.f;
            for (int k = 0; k < NBAND * RCG; ++k)
                s += g_part[(t * NBAND * RCG + k) * 8 + e];
            l[e] = s;
        }
        int i0 = 0; float m0 = l[0];
        #pragma unroll
        for (int e = 1; e < 8; ++e) if (l[e] > m0) { m0 = l[e]; i0 = e; }
        int i1 = (i0 == 0) ? 1 : 0; float m1 = l[i1];
        #pragma unroll
        for (int e = 0; e < 8; ++e)
            if (e != i0 && l[e] > m1) { m1 = l[e]; i1 = e; }
        float ex = expf(m1 - m0);
        float g0 = 1.f / (1.f + ex);
        float g1 = ex / (1.f + ex);
        g_sel[t * 2]     = i0;
        g_sel[t * 2 + 1] = i1;
        g_w1[t] = (g1 > 0.f) ? 1.f : 0.f;
        si0[t] = i0; si1[t] = i1; sg0[t] = g0; sg1[t] = g1;
    }
    __syncthreads();
    if (t == 0) {
        float imp[8]; float ldc[8];
        #pragma unroll
        for (int e = 0; e < 8; ++e) { imp[e] = 0.f; ldc[e] = 0.f; }
        for (int bb = 0; bb < Bz; ++bb) {
            imp[si0[bb]] += sg0[bb];
            imp[si1[bb]] += sg1[bb];
            ldc[si0[bb]] += 1.f;
            if (sg1[bb] > 0.f) ldc[si1[bb]] += 1.f;
        }
        float mi = 0.f, ml = 0.f;
        for (int e = 0; e < 8; ++e) { mi += imp[e]; ml += ldc[e]; }
        mi *= 0.125f; ml *= 0.125f;
        float vi = 0.f, vl = 0.f;
        for (int e = 0; e < 8; ++e) {
            float d  = imp[e] - mi; vi += d * d;
            float dl = ldc[e] - ml; vl += dl * dl;
        }
        vi *= (1.f / 7.f); vl *= (1.f / 7.f);
        float loss = (vi / (mi * mi + 1e-10f) + vl / (ml * ml + 1e-10f)) * 0.01f;
        out[loss_idx] = loss;
    }
}

// ============================================================
// Main fused kernel v8: v7 layout + cp.async.cg tile load.
// Tile cols now gw+4 (0..135, all 136 used), 16B-aligned chunks,
// halo via src_size=0 zero-fill. 4 ch/block, 4-row strips,
// 8 warps: warp = (row, ch-pair), serial 2-channel loop, 3 blocks/SM.
// ============================================================
#define MC4 4
#define MROW 10
#define MCOL 136                   // col = gw + 4; 34 x 16B chunks per row
#define MTILE (MC4 * MROW * MCOL)  // 5440 words
#define NCHUNK (MC4 * MROW * 34)   // 1360 16B chunks

__device__ __forceinline__ float lse_combine(float u, float v, float w1,
                                             float add) {
    float M = fmaxf(u, v);
    float lse = M + __logf(1.0f + __expf(-fabsf(u - v)));
    return ((w1 > 0.f) ? lse : u) + add;
}

__global__ __launch_bounds__(256, 3) void main_kernel(
    const float* __restrict__ x,    // [B,C,H,W]
    const float* __restrict__ ew,   // [E,C,1,7,7]
    const float* __restrict__ eb,   // [E,C]
    const float* __restrict__ sw,   // [C,1,7,7]
    const float* __restrict__ sb,   // [C]
    float* __restrict__ out)        // [B,HW,C]
{
    __shared__ __align__(16) float  sIn[MTILE];            // 21760 B
    __shared__ __align__(8)  float2 sWd[3 * MC4 * 49];     // 4704 B
    __shared__ __align__(16) float  sOut[MC4 * 4 * 128];   // 8192 B

    int hb = blockIdx.x;
    int cg = blockIdx.y;
    int b  = blockIdx.z;
    int h0 = hb * 4;
    int t  = threadIdx.x;
    int w  = t >> 5;
    int qx = t & 31;
    int r  = w & 3;
    int cp = w >> 2;

    int e0  = g_sel[b * 2];
    int e1i = g_sel[b * 2 + 1];
    float w1 = g_w1[b];

    const float* xb = x + ((long long)b * Cc + cg * MC4) * HWp;

    // ---- tile load via cp.async.cg (16B chunks, zfill halo) ----
    {
        unsigned int sbase = (unsigned int)__cvta_generic_to_shared(sIn);
        for (int k = t; k < NCHUNK; k += 256) {
            int c   = k / 340;               // 10*34 chunks per channel
            int rem = k - c * 340;
            int rr  = rem / 34;
            int c16 = rem - rr * 34;
            int gh  = h0 - 3 + rr;
            bool ok = (gh >= 0) & (gh < Hh) & (c16 >= 1) & (c16 <= 32);
            const float* src = ok ? (xb + c * HWp + gh * Ww + (c16 * 4 - 4)) : xb;
            int sz = ok ? 16 : 0;
            unsigned int dst = sbase + (unsigned int)((c * (MROW * MCOL) + rr * MCOL + c16 * 4) * 4);
            asm volatile("cp.async.cg.shared.global [%0], [%1], 16, %2;"
                         :: "r"(dst), "l"(src), "r"(sz) : "memory");
        }
        asm volatile("cp.async.commit_group;" ::: "memory");
    }
    // ---- duplicated weights [f][cl][49] as float2 (overlaps cp.async) ----
    for (int idx = t; idx < 3 * MC4 * 49; idx += 256) {
        int f   = idx / (MC4 * 49);
        int rem = idx - f * (MC4 * 49);
        int cl  = rem / 49;
        int k   = rem - cl * 49;
        int gc  = cg * MC4 + cl;
        float wv = (f == 0) ? sw[gc * 49 + k]
                 : (f == 1) ? ew[e0  * (Cc * 49) + gc * 49 + k]
                            : ew[e1i * (Cc * 49) + gc * 49 + k];
        sWd[idx] = make_float2(wv, wv);
    }
    asm volatile("cp.async.wait_group 0;" ::: "memory");
    __syncthreads();

    // ---- compute: loop 2 channels of this warp's pair ----
    #pragma unroll
    for (int ci = 0; ci < 2; ++ci) {
        int cl = cp * 2 + ci;
        const float* inc = sIn + cl * (MROW * MCOL) + qx * 4;
        const u64* wB = reinterpret_cast<const u64*>(sWd) + cl * 49;

        u64 acc[3][2];
        u64 z = pk(0.f, 0.f);
        #pragma unroll
        for (int f = 0; f < 3; ++f) { acc[f][0] = z; acc[f][1] = z; }

        #pragma unroll
        for (int dh = 0; dh < 7; ++dh) {
            const float* rp = inc + (r + dh) * MCOL;
            float4 v0 = *reinterpret_cast<const float4*>(rp);
            float4 v1 = *reinterpret_cast<const float4*>(rp + 4);
            float4 v2 = *reinterpret_cast<const float4*>(rp + 8);
            float tt[12];
            tt[0]=v0.x; tt[1]=v0.y; tt[2]=v0.z;  tt[3]=v0.w;
            tt[4]=v1.x; tt[5]=v1.y; tt[6]=v1.z;  tt[7]=v1.w;
            tt[8]=v2.x; tt[9]=v2.y; tt[10]=v2.z; tt[11]=v2.w;
            // output px j uses tap col px0 + 1 + j + dw  (col = gw + 4)
            u64 p[9];
            #pragma unroll
            for (int j = 0; j < 9; ++j) p[j] = pk(tt[j + 1], tt[j + 2]);
            #pragma unroll
            for (int f = 0; f < 3; ++f) {
                const u64* wf = wB + f * (MC4 * 49) + dh * 7;
                #pragma unroll
                for (int dw = 0; dw < 7; ++dw) {
                    u64 wv = wf[dw];                 // LDS.64 broadcast
                    fma2(acc[f][0], p[dw],     wv);  // px 0,1
                    fma2(acc[f][1], p[dw + 2], wv);  // px 2,3
                }
            }
        }

        // ---- LSE epilogue, stage to smem ----
        int gc = cg * MC4 + cl;
        float bS = sb[gc];
        float b0 = eb[e0  * Cc + gc];
        float b1 = eb[e1i * Cc + gc];

        float aS0,aS1,aS2,aS3, a00,a01,a02,a03, a10,a11,a12,a13;
        upk(acc[0][0], aS0, aS1); upk(acc[0][1], aS2, aS3);
        upk(acc[1][0], a00, a01); upk(acc[1][1], a02, a03);
        upk(acc[2][0], a10, a11); upk(acc[2][1], a12, a13);

        float4 res;
        res.x = lse_combine(a00 + b0, a10 + b1, w1, aS0 + bS);
        res.y = lse_combine(a01 + b0, a11 + b1, w1, aS1 + bS);
        res.z = lse_combine(a02 + b0, a12 + b1, w1, aS2 + bS);
        res.w = lse_combine(a03 + b0, a13 + b1, w1, aS3 + bS);
        *reinterpret_cast<float4*>(sOut + (cl * 4 + r) * 128 + qx * 4) = res;
    }
    __syncthreads();

    // ---- c-fastest store: STG.128 of 4 channels per px ----
    long long obase = ((long long)b * HWp + h0 * Ww) * Cc + cg * MC4;
    #pragma unroll
    for (int k = 0; k < 2; ++k) {
        int e   = t + k * 256;
        int row = e >> 7;
        int px  = e & 127;
        float4 v;
        v.x = sOut[(0 * 4 + row) * 128 + px];
        v.y = sOut[(1 * 4 + row) * 128 + px];
        v.z = sOut[(2 * 4 + row) * 128 + px];
        v.w = sOut[(3 * 4 + row) * 128 + px];
        *reinterpret_cast<float4*>(out + obase + (long long)(row * Ww + px) * Cc) = v;
    }
}

// ============================================================
extern "C" void kernel_launch(void* const* d_in, const int* in_sizes, int n_in,
                              void* d_out, int out_size) {
    const float* x  = (const float*)d_in[0];
    const float* rw = (const float*)d_in[1];
    const float* rb = (const float*)d_in[2];
    const float* wg = (const float*)d_in[3];
    const float* ew = (const float*)d_in[4];
    const float* eb = (const float*)d_in[5];
    const float* sw = (const float*)d_in[6];
    const float* sb = (const float*)d_in[7];
    float* out = (float*)d_out;

    router_kernel<<<dim3(Bz, NBAND, RCG), 256>>>(x, rw, rb, wg);
    gate_kernel<<<1, 32>>>(out, (long long)out_size - 1);
    main_kernel<<<dim3(Hh / 4, Cc / MC4, Bz), 256>>>(x, ew, eb, sw, sb, out);
}